// round 9
// baseline (speedup 1.0000x reference)
#include <cuda_runtime.h>
#include <math.h>
#include <stdint.h>

#define NB    2048
#define NC    9605
#define NL    20
#define NCP   9616                   // NC rounded up to 16
#define BDIM  256
#define CAP   2048
#define T1    2.5f                   // ~60 candidates expected for N(0,1)
#define T2    1.0f
#define TOTCH ((NB * NC) / 4)        // 4,917,610 int4 chunks (exact)
#define XBLK  1024                   // x-scan blocks (2 rows each)
#define ABLK  1184                   // activity-scan blocks
#define GRID  (XBLK + ABLK)

// Scratch (no allocations allowed)
__device__ __align__(16) unsigned char d_tabs[4][NCP]; // shifted class->group
__device__ int      d_hist[4];
__device__ int      d_actg[NB];      // per-row group-activity bitmask (y)
__device__ int      d_ang[NB];       // per-row group-activity bitmask (y_neg)
__device__ unsigned d_gmax[NB][NL];  // per-row fenc'd group maxima
__device__ float    d_v11[NB];       // per-row 11th-largest raw x
__device__ int      d_done;

// ---------------------------------------------------------------------------
// init + dtype detection fused (independent work items)
// ---------------------------------------------------------------------------
__global__ void __launch_bounds__(256)
initdetect_kernel(const unsigned char* __restrict__ raw) {
    int t0 = blockIdx.x * blockDim.x + threadIdx.x;
    int gs = gridDim.x * blockDim.x;
    if (t0 == 0) {
        d_done = 0;
        d_hist[0] = d_hist[1] = d_hist[2] = d_hist[3] = 0;
    }
    for (int i = t0; i < NB; i += gs) { d_actg[i] = 0; d_ang[i] = 0; }
    {
        uint4* p = (uint4*)d_tabs;
        const uint4 ff = make_uint4(0xFFFFFFFFu, 0xFFFFFFFFu,
                                    0xFFFFFFFFu, 0xFFFFFFFFu);
        for (int i = t0; i < (4 * NCP) / 16; i += gs) p[i] = ff;
    }
    // detect: flag nonzero bytes by (offset mod 4) over first NL*NC bytes
    const int total = NL * NC;
    const uint4* r4 = (const uint4*)raw;
    int f0 = 0, f1 = 0, f2 = 0, f3 = 0;
    int nv = total >> 4;
    for (int i = t0; i < nv; i += gs) {
        uint4 w = __ldg(r4 + i);
        unsigned a = w.x | w.y | w.z | w.w;
        f0 |= (a & 0x000000FFu) != 0;
        f1 |= (a & 0x0000FF00u) != 0;
        f2 |= (a & 0x00FF0000u) != 0;
        f3 |= (a & 0xFF000000u) != 0;
    }
    if (blockIdx.x == 0) {
        for (int i = (nv << 4) + threadIdx.x; i < total; i += blockDim.x)
            if (raw[i]) { int m = i & 3;
                f0 |= (m == 0); f1 |= (m == 1); f2 |= (m == 2); f3 |= (m == 3); }
    }
    if (f0) atomicOr(&d_hist[0], 1);
    if (f1) atomicOr(&d_hist[1], 1);
    if (f2) atomicOr(&d_hist[2], 1);
    if (f3) atomicOr(&d_hist[3], 1);
}

__device__ __forceinline__ void tab_set(int c, unsigned char g) {
#pragma unroll
    for (int h = 0; h < 4; ++h)
        if (c >= h) d_tabs[h][c - h] = g;
}

__global__ void __launch_bounds__(256)
build_kernel(const void* __restrict__ maskv) {
    int h0 = d_hist[0], h1 = d_hist[1], h2 = d_hist[2], h3 = d_hist[3];
    int mode;  // 0 = uint8, 1 = int32, 2 = float32
    if (h0 && !h1 && !h2 && !h3)        mode = 1;
    else if (!h0 && !h1 && (h2 || h3))  mode = 2;
    else                                 mode = 0;

    const int total = NL * NC;
    const int gs = gridDim.x * blockDim.x;
    const int t0 = blockIdx.x * blockDim.x + threadIdx.x;

    if (mode != 0) {
        const int4* m4 = (const int4*)maskv;  // int32/float32: !=0 bit test
        int nv = total >> 2;
        for (int i = t0; i < nv; i += gs) {
            int4 w = __ldg(m4 + i);
            int base = i << 2;
#pragma unroll
            for (int u = 0; u < 4; ++u) {
                int bits = (u == 0) ? w.x : (u == 1) ? w.y : (u == 2) ? w.z : w.w;
                if (bits != 0) {
                    int idx = base + u;
                    tab_set(idx % NC, (unsigned char)(idx / NC));
                }
            }
        }
        for (int idx = (nv << 2) + t0; idx < total; idx += gs)
            if (((const int*)maskv)[idx] != 0)
                tab_set(idx % NC, (unsigned char)(idx / NC));
    } else {
        const unsigned char* m8 = (const unsigned char*)maskv;
        for (int idx = t0; idx < total; idx += gs)
            if (m8[idx])
                tab_set(idx % NC, (unsigned char)(idx / NC));
    }
}

__device__ __forceinline__ float sigmoidf_(float v) {
    return 1.0f / (1.0f + expf(-v));
}
__device__ __forceinline__ float rankl(float x1, float x2) {
    float d = x2 - x1 + 0.05f;
    float s = 1.0f / (1.0f + expf(-10.0f * d));
    return (d > 0.0f) ? 2.0f * s : s;
}
__device__ __forceinline__ unsigned fenc(float v) {
    unsigned u = __float_as_uint(v);
    return (u & 0x80000000u) ? ~u : (u | 0x80000000u);
}
__device__ __forceinline__ float fdec(unsigned u) {
    return (u & 0x80000000u) ? __uint_as_float(u ^ 0x80000000u)
                             : __uint_as_float(~u);
}

__device__ __forceinline__ void act_hit(int i, const int4& w, int* dst) {
#pragma unroll
    for (int u = 0; u < 4; ++u) {
        int v = (u == 0) ? w.x : (u == 1) ? w.y : (u == 2) ? w.z : w.w;
        if (v != 0) {
            int q   = (i << 2) + u;
            int row = q / NC;                  // cold path: plain div OK
            int cls = q - row * NC;
            unsigned char t = d_tabs[0][cls];
            if (t != 0xFF) atomicOr(&dst[row], 1 << t);
        }
    }
}

// ---------------------------------------------------------------------------
// Heterogeneous main kernel: blocks [0, XBLK) scan x per-row (candidates +
// group max); blocks [XBLK, GRID) scan y/y_neg flat for activity bitmasks.
// Both run concurrently. Last block to finish computes all row losses + sum.
// ---------------------------------------------------------------------------
__global__ void __launch_bounds__(BDIM, 6)
main_kernel(const float* __restrict__ x,
            const int*   __restrict__ y,
            const int*   __restrict__ yn,
            float*       __restrict__ out) {
    const int tid = threadIdx.x;
    const int bid = blockIdx.x;

    __shared__ unsigned s_tabw[NCP / 4];
    __shared__ float    s_cand[CAP];
    __shared__ int      s_cnt;
    __shared__ float    s_v11;
    __shared__ unsigned s_gmax[NL];
    __shared__ int      s_last;

    if (bid < XBLK) {
        // ================= x-scan path: rows bid and bid + XBLK =============
        for (int b = bid; b < NB; b += XBLK) {
            const float* xr = x + (size_t)b * NC;

            if (tid == 0) s_cnt = 0;
            if (tid < NL) s_gmax[tid] = 0u;

            const int head = (int)((16u - ((unsigned)(uintptr_t)xr & 15u)) & 15u) >> 2;
            const float4* xv = (const float4*)(xr + head);
            const int nvec  = (NC - head) >> 2;
            const int tail0 = head + (nvec << 2);

            {
                const uint4* src = (const uint4*)d_tabs[head];
                uint4* dst = (uint4*)s_tabw;
                for (int i = tid; i < NCP / 16; i += BDIM) dst[i] = __ldg(src + i);
            }
            __syncthreads();

            auto process = [&](const float4& v, unsigned tw) {
                if (fmaxf(fmaxf(v.x, v.y), fmaxf(v.z, v.w)) > T1) {
                    if (v.x > T1) { int p = atomicAdd(&s_cnt, 1); if (p < CAP) s_cand[p] = v.x; }
                    if (v.y > T1) { int p = atomicAdd(&s_cnt, 1); if (p < CAP) s_cand[p] = v.y; }
                    if (v.z > T1) { int p = atomicAdd(&s_cnt, 1); if (p < CAP) s_cand[p] = v.z; }
                    if (v.w > T1) { int p = atomicAdd(&s_cnt, 1); if (p < CAP) s_cand[p] = v.w; }
                }
                if (tw != 0xFFFFFFFFu) {
                    unsigned t0 =  tw        & 0xFF;
                    unsigned t1 = (tw >> 8)  & 0xFF;
                    unsigned t2 = (tw >> 16) & 0xFF;
                    unsigned t3 = (tw >> 24) & 0xFF;
                    if (t0 != 0xFF) atomicMax(&s_gmax[t0], fenc(v.x));
                    if (t1 != 0xFF) atomicMax(&s_gmax[t1], fenc(v.y));
                    if (t2 != 0xFF) atomicMax(&s_gmax[t2], fenc(v.z));
                    if (t3 != 0xFF) atomicMax(&s_gmax[t3], fenc(v.w));
                }
            };
            auto scalar_at = [&](int c, unsigned char t) {
                float v = __ldg(xr + c);
                if (v > T1) { int p = atomicAdd(&s_cnt, 1); if (p < CAP) s_cand[p] = v; }
                if (t != 0xFF) atomicMax(&s_gmax[t], fenc(v));
            };

            if (tid < head) scalar_at(tid, d_tabs[0][tid]);

            int i = tid;
            for (; i + BDIM < nvec; i += 2 * BDIM) {
                float4 a0 = __ldcs(xv + i);
                float4 a1 = __ldcs(xv + i + BDIM);
                unsigned tw0 = s_tabw[i];
                unsigned tw1 = s_tabw[i + BDIM];
                process(a0, tw0);
                process(a1, tw1);
            }
            for (; i < nvec; i += BDIM)
                process(__ldcs(xv + i), s_tabw[i]);
            for (int c = tail0 + tid; c < NC; c += BDIM)
                scalar_at(c, ((const unsigned char*)s_tabw)[c - head]);

            __syncthreads();
            int cnt = s_cnt;

            // fallback tiers (unreachable for the bench distribution)
            auto rescan = [&](float thr, bool store) -> int {
                if (tid == 0) s_cnt = 0;
                __syncthreads();
                int local = 0;
                auto emit = [&](float v) {
                    if (v > thr) {
                        if (store) { int p = atomicAdd(&s_cnt, 1); if (p < CAP) s_cand[p] = v; }
                        else local++;
                    }
                };
                if (tid < head) emit(__ldg(xr + tid));
                for (int k = tid; k < nvec; k += BDIM) {
                    float4 v = __ldg(xv + k);
                    emit(v.x); emit(v.y); emit(v.z); emit(v.w);
                }
                for (int c = tail0 + tid; c < NC; c += BDIM) emit(__ldg(xr + c));
                if (!store && local) atomicAdd(&s_cnt, local);
                __syncthreads();
                return s_cnt;
            };

            if (cnt < 11 || cnt > CAP) {
                float thr = T2;
                cnt = rescan(thr, true);
                if (cnt < 11 || cnt > CAP) {
                    float tlo, thi;
                    if (cnt < 11) { thi = thr; tlo = -3.0e38f; }
                    else          { tlo = thr; thi = 3.0e38f; }
                    for (int it = 0; it < 120; ++it) {
                        float mid = 0.5f * (tlo + thi);
                        int c2 = rescan(mid, false);
                        if (c2 > CAP)      tlo = mid;
                        else if (c2 < 11)  thi = mid;
                        else { thr = mid; break; }
                        thr = mid;
                    }
                    cnt = rescan(thr, true);
                    if (cnt > CAP) cnt = CAP;
                }
            }

            // exact 11th largest among candidates
            for (int k = tid; k < cnt; k += BDIM) {
                float vi = s_cand[k];
                int rank = 0;
                for (int j = 0; j < cnt; ++j) {
                    float vj = s_cand[j];
                    rank += (vj > vi) || (vj == vi && j < k);
                }
                if (rank == 10) s_v11 = vi;
            }
            __syncthreads();

            if (tid < NL) d_gmax[b][tid] = s_gmax[tid];
            if (tid == 0) d_v11[b] = s_v11;
            __syncthreads();
        }
    } else {
        // ================= activity path: flat int4 scan of y and y_neg =====
        const int gs = ABLK * BDIM;
        const int4* y4 = (const int4*)y;
        const int4* n4 = (const int4*)yn;
        int i = (bid - XBLK) * BDIM + tid;
        for (; i + gs < TOTCH; i += 2 * gs) {
            int4 a0 = __ldcs(y4 + i);
            int4 a1 = __ldcs(y4 + i + gs);
            int4 b0 = __ldcs(n4 + i);
            int4 b1 = __ldcs(n4 + i + gs);
            if (a0.x | a0.y | a0.z | a0.w) act_hit(i,      a0, d_actg);
            if (a1.x | a1.y | a1.z | a1.w) act_hit(i + gs, a1, d_actg);
            if (b0.x | b0.y | b0.z | b0.w) act_hit(i,      b0, d_ang);
            if (b1.x | b1.y | b1.z | b1.w) act_hit(i + gs, b1, d_ang);
        }
        for (; i < TOTCH; i += gs) {
            int4 a = __ldcs(y4 + i);
            int4 b = __ldcs(n4 + i);
            if (a.x | a.y | a.z | a.w) act_hit(i, a, d_actg);
            if (b.x | b.y | b.z | b.w) act_hit(i, b, d_ang);
        }
    }

    // ---- completion counting; last block computes losses + deterministic sum
    if (tid == 0) {
        __threadfence();
        int done = atomicAdd(&d_done, 1);
        s_last = (done == GRID - 1);
    }
    __syncthreads();
    if (s_last) {
        __shared__ float sh[BDIM];
        float s = 0.0f;
        for (int b = tid; b < NB; b += BDIM) {      // fixed order per thread
            const float thres = fmaxf(sigmoidf_(d_v11[b]), 0.5f);
            const int act = d_actg[b];
            const int an  = d_ang[b];

            float umax = 0.0f, gssel = 0.0f, imax = 0.0f, ineg = 0.0f;
            int g = act ? (__ffs(act) - 1) : -1;
#pragma unroll
            for (int l = 0; l < NL; ++l) {
                float gl = sigmoidf_(fdec(d_gmax[b][l]));
                umax = fmaxf(umax, gl);
                if (l == g) gssel = gl;
                else        imax  = fmaxf(imax, gl);
                if (an & (1 << l)) ineg = fmaxf(ineg, gl);
            }

            float loss;
            if (g < 0) {
                loss = 0.5f * rankl(thres, umax) + 0.5f * rankl(thres, ineg);
            } else {
                loss = rankl(gssel, thres);
                if (imax > 0.0f) loss += 0.5f * rankl(thres, imax);
                loss += 0.5f * ((ineg > 0.0f) ? rankl(thres, ineg)
                                              : rankl(thres, imax));
            }
            s += loss;
        }
        sh[tid] = s;
        __syncthreads();
        for (int o = BDIM / 2; o > 0; o >>= 1) {
            if (tid < o) sh[tid] += sh[tid + o];
            __syncthreads();
        }
        if (tid == 0) out[0] = sh[0];
    }
}

extern "C" void kernel_launch(void* const* d_in, const int* in_sizes, int n_in,
                              void* d_out, int out_size) {
    const float* x    = (const float*)d_in[0];
    const int*   y    = (const int*)d_in[1];
    const int*   yn   = (const int*)d_in[2];
    const void*  mask = (const void*)d_in[3];
    float*       out  = (float*)d_out;

    initdetect_kernel<<<64, 256>>>((const unsigned char*)mask);
    build_kernel<<<148, 256>>>(mask);
    main_kernel<<<GRID, BDIM>>>(x, y, yn, out);
}

// round 10
// speedup vs baseline: 1.2555x; 1.2555x over previous
#include <cuda_runtime.h>
#include <math.h>
#include <stdint.h>

#define NB    2048
#define NC    9605
#define NL    20
#define NCP   9616                    // NC rounded up to 16
#define BDIM  256
#define CCAP  768                     // per-row candidate capacity
#define T1    2.5f                    // ~60 candidates expected for N(0,1)
#define TOTCH ((NB * NC) / 4)         // 4,917,760 int4 chunks (exact)
#define GRIDM 4736
#define SPAN  ((TOTCH + GRIDM - 1) / GRIDM)   // 1039 chunks (< 1 row)

// Scratch (no allocations allowed)
__device__ __align__(16) unsigned char d_tabs[4][NCP]; // shifted class->group
__device__ int      d_hist[4];
__device__ int      d_actg[NB];       // per-row group-activity bitmask (y)
__device__ int      d_ang[NB];        // per-row group-activity bitmask (y_neg)
__device__ unsigned d_gmax[NB][NL];   // per-row fenc'd group maxima
__device__ int      d_ccnt[NB];       // per-row candidate counts
__device__ float    d_cand[NB][CCAP]; // per-row candidate values
__device__ float    d_loss[NB];
__device__ int      d_done2;

// ---------------------------------------------------------------------------
// init + dtype detection fused
// ---------------------------------------------------------------------------
__global__ void __launch_bounds__(256)
initdetect_kernel(const unsigned char* __restrict__ raw) {
    int t0 = blockIdx.x * blockDim.x + threadIdx.x;
    int gs = gridDim.x * blockDim.x;
    if (t0 == 0) {
        d_done2 = 0;
        d_hist[0] = d_hist[1] = d_hist[2] = d_hist[3] = 0;
    }
    for (int i = t0; i < NB; i += gs) { d_actg[i] = 0; d_ang[i] = 0; d_ccnt[i] = 0; }
    for (int i = t0; i < NB * NL; i += gs) ((unsigned*)d_gmax)[i] = 0u;
    {
        uint4* p = (uint4*)d_tabs;
        const uint4 ff = make_uint4(0xFFFFFFFFu, 0xFFFFFFFFu,
                                    0xFFFFFFFFu, 0xFFFFFFFFu);
        for (int i = t0; i < (4 * NCP) / 16; i += gs) p[i] = ff;
    }
    // detect: flag nonzero bytes by (offset mod 4) over first NL*NC bytes
    const int total = NL * NC;
    const uint4* r4 = (const uint4*)raw;
    int f0 = 0, f1 = 0, f2 = 0, f3 = 0;
    int nv = total >> 4;
    for (int i = t0; i < nv; i += gs) {
        uint4 w = __ldg(r4 + i);
        unsigned a = w.x | w.y | w.z | w.w;
        f0 |= (a & 0x000000FFu) != 0;
        f1 |= (a & 0x0000FF00u) != 0;
        f2 |= (a & 0x00FF0000u) != 0;
        f3 |= (a & 0xFF000000u) != 0;
    }
    if (blockIdx.x == 0) {
        for (int i = (nv << 4) + threadIdx.x; i < total; i += blockDim.x)
            if (raw[i]) { int m = i & 3;
                f0 |= (m == 0); f1 |= (m == 1); f2 |= (m == 2); f3 |= (m == 3); }
    }
    if (f0) atomicOr(&d_hist[0], 1);
    if (f1) atomicOr(&d_hist[1], 1);
    if (f2) atomicOr(&d_hist[2], 1);
    if (f3) atomicOr(&d_hist[3], 1);
}

__device__ __forceinline__ void tab_set(int c, unsigned char g) {
#pragma unroll
    for (int h = 0; h < 4; ++h)
        if (c >= h) d_tabs[h][c - h] = g;
}

__global__ void __launch_bounds__(256)
build_kernel(const void* __restrict__ maskv) {
    int h0 = d_hist[0], h1 = d_hist[1], h2 = d_hist[2], h3 = d_hist[3];
    int mode;  // 0 = uint8, 1 = int32, 2 = float32
    if (h0 && !h1 && !h2 && !h3)        mode = 1;
    else if (!h0 && !h1 && (h2 || h3))  mode = 2;
    else                                 mode = 0;

    const int total = NL * NC;
    const int gs = gridDim.x * blockDim.x;
    const int t0 = blockIdx.x * blockDim.x + threadIdx.x;

    if (mode != 0) {
        const int4* m4 = (const int4*)maskv;  // int32/float32: !=0 bit test
        int nv = total >> 2;
        for (int i = t0; i < nv; i += gs) {
            int4 w = __ldg(m4 + i);
            int base = i << 2;
#pragma unroll
            for (int u = 0; u < 4; ++u) {
                int bits = (u == 0) ? w.x : (u == 1) ? w.y : (u == 2) ? w.z : w.w;
                if (bits != 0) {
                    int idx = base + u;
                    tab_set(idx % NC, (unsigned char)(idx / NC));
                }
            }
        }
        for (int idx = (nv << 2) + t0; idx < total; idx += gs)
            if (((const int*)maskv)[idx] != 0)
                tab_set(idx % NC, (unsigned char)(idx / NC));
    } else {
        const unsigned char* m8 = (const unsigned char*)maskv;
        for (int idx = t0; idx < total; idx += gs)
            if (m8[idx])
                tab_set(idx % NC, (unsigned char)(idx / NC));
    }
}

__device__ __forceinline__ float sigmoidf_(float v) {
    return 1.0f / (1.0f + expf(-v));
}
__device__ __forceinline__ float rankl(float x1, float x2) {
    float d = x2 - x1 + 0.05f;
    float s = 1.0f / (1.0f + expf(-10.0f * d));
    return (d > 0.0f) ? 2.0f * s : s;
}
__device__ __forceinline__ unsigned fenc(float v) {
    unsigned u = __float_as_uint(v);
    return (u & 0x80000000u) ? ~u : (u | 0x80000000u);
}
__device__ __forceinline__ float fdec(unsigned u) {
    return (u & 0x80000000u) ? __uint_as_float(u ^ 0x80000000u)
                             : __uint_as_float(~u);
}

// ---------------------------------------------------------------------------
// Fused flat scan: each block owns a contiguous chunk span (< 1 row) and
// streams x / y / y_neg at the same indices. Candidates -> global per-row
// buffers; group max -> smem accumulation (<=3 rows) flushed once; activity ->
// rare global atomicOr.
// ---------------------------------------------------------------------------
__global__ void __launch_bounds__(BDIM, 6)
scan_kernel(const float* __restrict__ x,
            const int*   __restrict__ y,
            const int*   __restrict__ yn) {
    const int tid = threadIdx.x;
    const int c0 = blockIdx.x * SPAN;
    const int c1 = (c0 + SPAN < TOTCH) ? c0 + SPAN : TOTCH;

    __shared__ unsigned s_g[3][NL];
    if (tid < 3 * NL) s_g[tid / NL][tid % NL] = 0u;
    __syncthreads();

    const int r0 = (c0 < TOTCH) ? ((c0 << 2) / NC) : NB;
    const float4* x4 = (const float4*)x;
    const int4*   y4 = (const int4*)y;
    const int4*   n4 = (const int4*)yn;

    auto proc = [&](int i, const float4& v, const int4& yq, const int4& nq) {
        const int q   = i << 2;
        const int row = q / NC;
        const int cls = q - row * NC;
        const int ro  = row - r0;
        if (cls <= NC - 4) {
            // hot path: all 4 classes in one row
            const unsigned h = (unsigned)cls & 3u;
            const unsigned tw = __ldg((const unsigned*)(d_tabs[h]) + ((cls - (int)h) >> 2));
            if (fmaxf(fmaxf(v.x, v.y), fmaxf(v.z, v.w)) > T1) {
                if (v.x > T1) { int p = atomicAdd(&d_ccnt[row], 1); if (p < CCAP) d_cand[row][p] = v.x; }
                if (v.y > T1) { int p = atomicAdd(&d_ccnt[row], 1); if (p < CCAP) d_cand[row][p] = v.y; }
                if (v.z > T1) { int p = atomicAdd(&d_ccnt[row], 1); if (p < CCAP) d_cand[row][p] = v.z; }
                if (v.w > T1) { int p = atomicAdd(&d_ccnt[row], 1); if (p < CCAP) d_cand[row][p] = v.w; }
            }
            if (tw != 0xFFFFFFFFu) {
                unsigned t0b =  tw        & 0xFF;
                unsigned t1b = (tw >> 8)  & 0xFF;
                unsigned t2b = (tw >> 16) & 0xFF;
                unsigned t3b = (tw >> 24) & 0xFF;
                if (t0b != 0xFF) atomicMax(&s_g[ro][t0b], fenc(v.x));
                if (t1b != 0xFF) atomicMax(&s_g[ro][t1b], fenc(v.y));
                if (t2b != 0xFF) atomicMax(&s_g[ro][t2b], fenc(v.z));
                if (t3b != 0xFF) atomicMax(&s_g[ro][t3b], fenc(v.w));
            }
            if (yq.x | yq.y | yq.z | yq.w) {
                if (yq.x) { unsigned t = tw & 0xFF;         if (t != 0xFF) atomicOr(&d_actg[row], 1 << t); }
                if (yq.y) { unsigned t = (tw >> 8) & 0xFF;  if (t != 0xFF) atomicOr(&d_actg[row], 1 << t); }
                if (yq.z) { unsigned t = (tw >> 16) & 0xFF; if (t != 0xFF) atomicOr(&d_actg[row], 1 << t); }
                if (yq.w) { unsigned t = (tw >> 24) & 0xFF; if (t != 0xFF) atomicOr(&d_actg[row], 1 << t); }
            }
            if (nq.x | nq.y | nq.z | nq.w) {
                if (nq.x) { unsigned t = tw & 0xFF;         if (t != 0xFF) atomicOr(&d_ang[row], 1 << t); }
                if (nq.y) { unsigned t = (tw >> 8) & 0xFF;  if (t != 0xFF) atomicOr(&d_ang[row], 1 << t); }
                if (nq.z) { unsigned t = (tw >> 16) & 0xFF; if (t != 0xFF) atomicOr(&d_ang[row], 1 << t); }
                if (nq.w) { unsigned t = (tw >> 24) & 0xFF; if (t != 0xFF) atomicOr(&d_ang[row], 1 << t); }
            }
        } else {
            // boundary chunk straddling a row edge: elementwise (rare)
#pragma unroll
            for (int u = 0; u < 4; ++u) {
                float v1  = (u == 0) ? v.x : (u == 1) ? v.y : (u == 2) ? v.z : v.w;
                int   yv1 = (u == 0) ? yq.x : (u == 1) ? yq.y : (u == 2) ? yq.z : yq.w;
                int   nv1 = (u == 0) ? nq.x : (u == 1) ? nq.y : (u == 2) ? nq.z : nq.w;
                int qk   = q + u;
                int rk   = qk / NC;
                int ck   = qk - rk * NC;
                if (v1 > T1) { int p = atomicAdd(&d_ccnt[rk], 1); if (p < CCAP) d_cand[rk][p] = v1; }
                unsigned t = __ldg(&d_tabs[0][ck]);
                if (t != 0xFF) {
                    int rok = rk - r0;
                    if (rok >= 0 && rok < 3) atomicMax(&s_g[rok][t], fenc(v1));
                    else                     atomicMax(&d_gmax[rk][t], fenc(v1));
                    if (yv1) atomicOr(&d_actg[rk], 1 << t);
                    if (nv1) atomicOr(&d_ang[rk],  1 << t);
                }
            }
        }
    };

    int i = c0 + tid;
    for (; i + BDIM < c1; i += 2 * BDIM) {
        float4 a0 = __ldcs(x4 + i);
        float4 a1 = __ldcs(x4 + i + BDIM);
        int4   b0 = __ldcs(y4 + i);
        int4   b1 = __ldcs(y4 + i + BDIM);
        int4   e0 = __ldcs(n4 + i);
        int4   e1 = __ldcs(n4 + i + BDIM);
        proc(i, a0, b0, e0);
        proc(i + BDIM, a1, b1, e1);
    }
    for (; i < c1; i += BDIM) {
        float4 a = __ldcs(x4 + i);
        int4   b = __ldcs(y4 + i);
        int4   e = __ldcs(n4 + i);
        proc(i, a, b, e);
    }

    __syncthreads();
    if (tid < 3 * NL) {
        int ro = tid / NL, l = tid % NL;
        int row = r0 + ro;
        unsigned v = s_g[ro][l];
        if (v && row < NB) atomicMax(&d_gmax[row][l], v);
    }
}

// ---------------------------------------------------------------------------
// Phase 2: warp per row. Exact 11th-largest from candidates (bisection
// fallback for correctness), loss math, deterministic final reduction.
// ---------------------------------------------------------------------------
__global__ void __launch_bounds__(BDIM)
loss_kernel(const float* __restrict__ x, float* __restrict__ out) {
    const int tid  = threadIdx.x;
    const int w    = tid >> 5;
    const int lane = tid & 31;
    const int b    = blockIdx.x * 8 + w;

    __shared__ float s_v[8];
    __shared__ int   s_last;

    {
        int cnt = d_ccnt[b];
        const float* xr = x + (size_t)b * NC;

        if (cnt < 11 || cnt > CCAP) {
            // bisection fallback (unreachable for the bench distribution)
            float tlo = -3.0e38f, thi = 3.0e38f, thr = T1;
            for (int it = 0; it < 120; ++it) {
                int local = 0;
                for (int c = lane; c < NC; c += 32) local += (__ldg(xr + c) > thr);
#pragma unroll
                for (int o = 16; o > 0; o >>= 1)
                    local += __shfl_down_sync(0xffffffffu, local, o);
                int c2 = __shfl_sync(0xffffffffu, local, 0);
                if (c2 > CCAP)      { tlo = thr; }
                else if (c2 < 11)   { thi = thr; }
                else break;
                thr = 0.5f * (tlo + thi);
            }
            if (lane == 0) d_ccnt[b] = 0;
            __syncwarp();
            for (int c = lane; c < NC; c += 32) {
                float v = __ldg(xr + c);
                if (v > thr) {
                    int p = atomicAdd(&d_ccnt[b], 1);
                    if (p < CCAP) d_cand[b][p] = v;
                }
            }
            __syncwarp();
            cnt = d_ccnt[b];
            if (cnt > CCAP) cnt = CCAP;
        }

        // exact 11th largest via rank counting (warp-parallel)
        for (int i2 = lane; i2 < cnt; i2 += 32) {
            float vi = d_cand[b][i2];
            int rank = 0;
            for (int j = 0; j < cnt; ++j) {
                float vj = d_cand[b][j];
                rank += (vj > vi) || (vj == vi && j < i2);
            }
            if (rank == 10) s_v[w] = vi;
        }
        __syncwarp();

        if (lane == 0) {
            const float thres = fmaxf(sigmoidf_(s_v[w]), 0.5f);
            const int act = d_actg[b];
            const int an  = d_ang[b];

            float umax = 0.0f, gssel = 0.0f, imax = 0.0f, ineg = 0.0f;
            int g = act ? (__ffs(act) - 1) : -1;
#pragma unroll
            for (int l = 0; l < NL; ++l) {
                float gl = sigmoidf_(fdec(d_gmax[b][l]));
                umax = fmaxf(umax, gl);
                if (l == g) gssel = gl;
                else        imax  = fmaxf(imax, gl);
                if (an & (1 << l)) ineg = fmaxf(ineg, gl);
            }

            float loss;
            if (g < 0) {
                loss = 0.5f * rankl(thres, umax) + 0.5f * rankl(thres, ineg);
            } else {
                loss = rankl(gssel, thres);
                if (imax > 0.0f) loss += 0.5f * rankl(thres, imax);
                loss += 0.5f * ((ineg > 0.0f) ? rankl(thres, ineg)
                                              : rankl(thres, imax));
            }
            d_loss[b] = loss;
        }
    }

    __syncthreads();
    if (tid == 0) {
        __threadfence();
        int done = atomicAdd(&d_done2, 1);
        s_last = (done == NB / 8 - 1);
    }
    __syncthreads();
    if (s_last) {
        __shared__ float sh[BDIM];
        float s = 0.0f;
#pragma unroll
        for (int k = 0; k < NB / BDIM; ++k)
            s += d_loss[tid + k * BDIM];
        sh[tid] = s;
        __syncthreads();
        for (int o = BDIM / 2; o > 0; o >>= 1) {
            if (tid < o) sh[tid] += sh[tid + o];
            __syncthreads();
        }
        if (tid == 0) out[0] = sh[0];
    }
}

extern "C" void kernel_launch(void* const* d_in, const int* in_sizes, int n_in,
                              void* d_out, int out_size) {
    const float* x    = (const float*)d_in[0];
    const int*   y    = (const int*)d_in[1];
    const int*   yn   = (const int*)d_in[2];
    const void*  mask = (const void*)d_in[3];
    float*       out  = (float*)d_out;

    initdetect_kernel<<<256, 256>>>((const unsigned char*)mask);
    build_kernel<<<592, 256>>>(mask);
    scan_kernel<<<GRIDM, BDIM>>>(x, y, yn);
    loss_kernel<<<NB / 8, BDIM>>>(x, out);
}

// round 11
// speedup vs baseline: 1.2864x; 1.0246x over previous
#include <cuda_runtime.h>
#include <math.h>
#include <stdint.h>
#include <float.h>

#define NB    2048
#define NC    9605
#define NL    20
#define NCP   9616                    // NC rounded up to 16
#define BDIM  256
#define CCAP  768                     // per-row candidate capacity
#define T1    2.5f                    // ~60 candidates expected for N(0,1)
#define TOTCH ((NB * NC) / 4)         // int4 chunks (exact: NB*NC % 4 == 0)
#define GRIDM 4736
#define SPAN  ((TOTCH + GRIDM - 1) / GRIDM)

// Scratch (no allocations allowed)
__device__ __align__(16) unsigned char d_tabs[4][NCP]; // shifted class->group
__device__ int      d_hist[4];
__device__ int      d_actg[NB];       // per-row group-activity bitmask (y)
__device__ int      d_ang[NB];        // per-row group-activity bitmask (y_neg)
__device__ unsigned d_gmax[NB][NL];   // per-row fenc'd group maxima
__device__ int      d_ccnt[NB];       // per-row candidate counts
__device__ float    d_cand[NB][CCAP]; // per-row candidate values
__device__ float    d_loss[NB];
__device__ int      d_done2;

// ---------------------------------------------------------------------------
// init + dtype detection fused
// ---------------------------------------------------------------------------
__global__ void __launch_bounds__(256)
initdetect_kernel(const unsigned char* __restrict__ raw) {
    int t0 = blockIdx.x * blockDim.x + threadIdx.x;
    int gs = gridDim.x * blockDim.x;
    if (t0 == 0) {
        d_done2 = 0;
        d_hist[0] = d_hist[1] = d_hist[2] = d_hist[3] = 0;
    }
    for (int i = t0; i < NB; i += gs) { d_actg[i] = 0; d_ang[i] = 0; d_ccnt[i] = 0; }
    for (int i = t0; i < NB * NL; i += gs) ((unsigned*)d_gmax)[i] = 0u;
    {
        uint4* p = (uint4*)d_tabs;
        const uint4 ff = make_uint4(0xFFFFFFFFu, 0xFFFFFFFFu,
                                    0xFFFFFFFFu, 0xFFFFFFFFu);
        for (int i = t0; i < (4 * NCP) / 16; i += gs) p[i] = ff;
    }
    // detect: flag nonzero bytes by (offset mod 4) over first NL*NC bytes
    const int total = NL * NC;
    const uint4* r4 = (const uint4*)raw;
    int f0 = 0, f1 = 0, f2 = 0, f3 = 0;
    int nv = total >> 4;
    for (int i = t0; i < nv; i += gs) {
        uint4 w = __ldg(r4 + i);
        unsigned a = w.x | w.y | w.z | w.w;
        f0 |= (a & 0x000000FFu) != 0;
        f1 |= (a & 0x0000FF00u) != 0;
        f2 |= (a & 0x00FF0000u) != 0;
        f3 |= (a & 0xFF000000u) != 0;
    }
    if (blockIdx.x == 0) {
        for (int i = (nv << 4) + threadIdx.x; i < total; i += blockDim.x)
            if (raw[i]) { int m = i & 3;
                f0 |= (m == 0); f1 |= (m == 1); f2 |= (m == 2); f3 |= (m == 3); }
    }
    if (f0) atomicOr(&d_hist[0], 1);
    if (f1) atomicOr(&d_hist[1], 1);
    if (f2) atomicOr(&d_hist[2], 1);
    if (f3) atomicOr(&d_hist[3], 1);
}

__device__ __forceinline__ void tab_set(int c, unsigned char g) {
#pragma unroll
    for (int h = 0; h < 4; ++h)
        if (c >= h) d_tabs[h][c - h] = g;
}

__global__ void __launch_bounds__(256)
build_kernel(const void* __restrict__ maskv) {
    int h0 = d_hist[0], h1 = d_hist[1], h2 = d_hist[2], h3 = d_hist[3];
    int mode;  // 0 = uint8, 1 = int32, 2 = float32
    if (h0 && !h1 && !h2 && !h3)        mode = 1;
    else if (!h0 && !h1 && (h2 || h3))  mode = 2;
    else                                 mode = 0;

    const int total = NL * NC;
    const int gs = gridDim.x * blockDim.x;
    const int t0 = blockIdx.x * blockDim.x + threadIdx.x;

    if (mode != 0) {
        const int4* m4 = (const int4*)maskv;  // int32/float32: !=0 bit test
        int nv = total >> 2;
        for (int i = t0; i < nv; i += gs) {
            int4 w = __ldg(m4 + i);
            int base = i << 2;
#pragma unroll
            for (int u = 0; u < 4; ++u) {
                int bits = (u == 0) ? w.x : (u == 1) ? w.y : (u == 2) ? w.z : w.w;
                if (bits != 0) {
                    int idx = base + u;
                    tab_set(idx % NC, (unsigned char)(idx / NC));
                }
            }
        }
        for (int idx = (nv << 2) + t0; idx < total; idx += gs)
            if (((const int*)maskv)[idx] != 0)
                tab_set(idx % NC, (unsigned char)(idx / NC));
    } else {
        const unsigned char* m8 = (const unsigned char*)maskv;
        for (int idx = t0; idx < total; idx += gs)
            if (m8[idx])
                tab_set(idx % NC, (unsigned char)(idx / NC));
    }
}

__device__ __forceinline__ float sigmoidf_(float v) {
    return 1.0f / (1.0f + expf(-v));
}
__device__ __forceinline__ float rankl(float x1, float x2) {
    float d = x2 - x1 + 0.05f;
    float s = 1.0f / (1.0f + expf(-10.0f * d));
    return (d > 0.0f) ? 2.0f * s : s;
}
__device__ __forceinline__ unsigned fenc(float v) {
    unsigned u = __float_as_uint(v);
    return (u & 0x80000000u) ? ~u : (u | 0x80000000u);
}
__device__ __forceinline__ float fdec(unsigned u) {
    return (u & 0x80000000u) ? __uint_as_float(u ^ 0x80000000u)
                             : __uint_as_float(~u);
}

// ---------------------------------------------------------------------------
// Fused flat scan: each block owns a contiguous chunk span (< 1 row) and
// streams x / y / y_neg at the same indices.
// ---------------------------------------------------------------------------
__global__ void __launch_bounds__(BDIM, 6)
scan_kernel(const float* __restrict__ x,
            const int*   __restrict__ y,
            const int*   __restrict__ yn) {
    const int tid = threadIdx.x;
    const int c0 = blockIdx.x * SPAN;
    const int c1 = (c0 + SPAN < TOTCH) ? c0 + SPAN : TOTCH;

    __shared__ unsigned s_g[3][NL];
    if (tid < 3 * NL) s_g[tid / NL][tid % NL] = 0u;
    __syncthreads();

    const int r0 = (c0 < TOTCH) ? ((c0 << 2) / NC) : NB;
    const float4* x4 = (const float4*)x;
    const int4*   y4 = (const int4*)y;
    const int4*   n4 = (const int4*)yn;

    auto proc = [&](int i, const float4& v, const int4& yq, const int4& nq) {
        const int q   = i << 2;
        const int row = q / NC;
        const int cls = q - row * NC;
        const int ro  = row - r0;
        if (cls <= NC - 4) {
            // hot path: all 4 classes in one row
            const unsigned h = (unsigned)cls & 3u;
            const unsigned tw = __ldg((const unsigned*)(d_tabs[h]) + ((cls - (int)h) >> 2));
            if (fmaxf(fmaxf(v.x, v.y), fmaxf(v.z, v.w)) > T1) {
                if (v.x > T1) { int p = atomicAdd(&d_ccnt[row], 1); if (p < CCAP) d_cand[row][p] = v.x; }
                if (v.y > T1) { int p = atomicAdd(&d_ccnt[row], 1); if (p < CCAP) d_cand[row][p] = v.y; }
                if (v.z > T1) { int p = atomicAdd(&d_ccnt[row], 1); if (p < CCAP) d_cand[row][p] = v.z; }
                if (v.w > T1) { int p = atomicAdd(&d_ccnt[row], 1); if (p < CCAP) d_cand[row][p] = v.w; }
            }
            if (tw != 0xFFFFFFFFu) {
                unsigned t0b =  tw        & 0xFF;
                unsigned t1b = (tw >> 8)  & 0xFF;
                unsigned t2b = (tw >> 16) & 0xFF;
                unsigned t3b = (tw >> 24) & 0xFF;
                if (t0b != 0xFF) atomicMax(&s_g[ro][t0b], fenc(v.x));
                if (t1b != 0xFF) atomicMax(&s_g[ro][t1b], fenc(v.y));
                if (t2b != 0xFF) atomicMax(&s_g[ro][t2b], fenc(v.z));
                if (t3b != 0xFF) atomicMax(&s_g[ro][t3b], fenc(v.w));
            }
            if (yq.x | yq.y | yq.z | yq.w) {
                if (yq.x) { unsigned t = tw & 0xFF;         if (t != 0xFF) atomicOr(&d_actg[row], 1 << t); }
                if (yq.y) { unsigned t = (tw >> 8) & 0xFF;  if (t != 0xFF) atomicOr(&d_actg[row], 1 << t); }
                if (yq.z) { unsigned t = (tw >> 16) & 0xFF; if (t != 0xFF) atomicOr(&d_actg[row], 1 << t); }
                if (yq.w) { unsigned t = (tw >> 24) & 0xFF; if (t != 0xFF) atomicOr(&d_actg[row], 1 << t); }
            }
            if (nq.x | nq.y | nq.z | nq.w) {
                if (nq.x) { unsigned t = tw & 0xFF;         if (t != 0xFF) atomicOr(&d_ang[row], 1 << t); }
                if (nq.y) { unsigned t = (tw >> 8) & 0xFF;  if (t != 0xFF) atomicOr(&d_ang[row], 1 << t); }
                if (nq.z) { unsigned t = (tw >> 16) & 0xFF; if (t != 0xFF) atomicOr(&d_ang[row], 1 << t); }
                if (nq.w) { unsigned t = (tw >> 24) & 0xFF; if (t != 0xFF) atomicOr(&d_ang[row], 1 << t); }
            }
        } else {
            // boundary chunk straddling a row edge (rare)
#pragma unroll
            for (int u = 0; u < 4; ++u) {
                float v1  = (u == 0) ? v.x : (u == 1) ? v.y : (u == 2) ? v.z : v.w;
                int   yv1 = (u == 0) ? yq.x : (u == 1) ? yq.y : (u == 2) ? yq.z : yq.w;
                int   nv1 = (u == 0) ? nq.x : (u == 1) ? nq.y : (u == 2) ? nq.z : nq.w;
                int qk   = q + u;
                int rk   = qk / NC;
                int ck   = qk - rk * NC;
                if (v1 > T1) { int p = atomicAdd(&d_ccnt[rk], 1); if (p < CCAP) d_cand[rk][p] = v1; }
                unsigned t = __ldg(&d_tabs[0][ck]);
                if (t != 0xFF) {
                    int rok = rk - r0;
                    if (rok >= 0 && rok < 3) atomicMax(&s_g[rok][t], fenc(v1));
                    else                     atomicMax(&d_gmax[rk][t], fenc(v1));
                    if (yv1) atomicOr(&d_actg[rk], 1 << t);
                    if (nv1) atomicOr(&d_ang[rk],  1 << t);
                }
            }
        }
    };

    int i = c0 + tid;
    for (; i + BDIM < c1; i += 2 * BDIM) {
        float4 a0 = __ldcs(x4 + i);
        float4 a1 = __ldcs(x4 + i + BDIM);
        int4   b0 = __ldcs(y4 + i);
        int4   b1 = __ldcs(y4 + i + BDIM);
        int4   e0 = __ldcs(n4 + i);
        int4   e1 = __ldcs(n4 + i + BDIM);
        proc(i, a0, b0, e0);
        proc(i + BDIM, a1, b1, e1);
    }
    for (; i < c1; i += BDIM) {
        float4 a = __ldcs(x4 + i);
        int4   b = __ldcs(y4 + i);
        int4   e = __ldcs(n4 + i);
        proc(i, a, b, e);
    }

    __syncthreads();
    if (tid < 3 * NL) {
        int ro = tid / NL, l = tid % NL;
        int row = r0 + ro;
        unsigned v = s_g[ro][l];
        if (v && row < NB) atomicMax(&d_gmax[row][l], v);
    }
}

// ---------------------------------------------------------------------------
// Phase 2: warp per row. Register-resident 11th-largest extraction (cnt<=128
// fast path), fallbacks for exactness, loss math, deterministic reduction.
// ---------------------------------------------------------------------------
__global__ void __launch_bounds__(BDIM)
loss_kernel(const float* __restrict__ x, float* __restrict__ out) {
    const int tid  = threadIdx.x;
    const int w    = tid >> 5;
    const int lane = tid & 31;
    const int b    = blockIdx.x * 8 + w;

    __shared__ int s_last;

    {
        int cnt = d_ccnt[b];
        const float* xr = x + (size_t)b * NC;

        if (cnt < 11 || cnt > CCAP) {
            // bisection fallback (unreachable for the bench distribution)
            float tlo = -3.0e38f, thi = 3.0e38f, thr = T1;
            for (int it = 0; it < 120; ++it) {
                int local = 0;
                for (int c = lane; c < NC; c += 32) local += (__ldg(xr + c) > thr);
#pragma unroll
                for (int o = 16; o > 0; o >>= 1)
                    local += __shfl_down_sync(0xffffffffu, local, o);
                int c2 = __shfl_sync(0xffffffffu, local, 0);
                if (c2 > 128)       { tlo = thr; }
                else if (c2 < 11)   { thi = thr; }
                else break;
                thr = 0.5f * (tlo + thi);
            }
            if (lane == 0) d_ccnt[b] = 0;
            __syncwarp();
            for (int c = lane; c < NC; c += 32) {
                float v = __ldg(xr + c);
                if (v > thr) {
                    int p = atomicAdd(&d_ccnt[b], 1);
                    if (p < CCAP) d_cand[b][p] = v;
                }
            }
            __syncwarp();
            cnt = d_ccnt[b];
            if (cnt > CCAP) cnt = CCAP;
        }

        float v11;
        if (cnt <= 128) {
            // register-resident extraction: 4 candidates per lane, 11 rounds
            float v0 = (lane       < cnt) ? d_cand[b][lane]       : -FLT_MAX;
            float v1 = (lane + 32  < cnt) ? d_cand[b][lane + 32]  : -FLT_MAX;
            float v2 = (lane + 64  < cnt) ? d_cand[b][lane + 64]  : -FLT_MAX;
            float v3 = (lane + 96  < cnt) ? d_cand[b][lane + 96]  : -FLT_MAX;
            v11 = -FLT_MAX;
#pragma unroll
            for (int r = 0; r < 11; ++r) {
                float lm = fmaxf(fmaxf(v0, v1), fmaxf(v2, v3));
                float m = lm;
#pragma unroll
                for (int o = 16; o > 0; o >>= 1)
                    m = fmaxf(m, __shfl_xor_sync(0xffffffffu, m, o));
                if (r == 10) { v11 = m; break; }
                unsigned ballot = __ballot_sync(0xffffffffu, lm == m);
                int owner = __ffs(ballot) - 1;
                if (lane == owner) {
                    if      (v0 == m) v0 = -FLT_MAX;
                    else if (v1 == m) v1 = -FLT_MAX;
                    else if (v2 == m) v2 = -FLT_MAX;
                    else              v3 = -FLT_MAX;
                }
            }
        } else {
            // rank-count fallback for 128 < cnt <= CCAP
            float found = -FLT_MAX;
            for (int i2 = lane; i2 < cnt; i2 += 32) {
                float vi = d_cand[b][i2];
                int rank = 0;
                for (int j = 0; j < cnt; ++j) {
                    float vj = d_cand[b][j];
                    rank += (vj > vi) || (vj == vi && j < i2);
                }
                if (rank == 10) found = vi;
            }
#pragma unroll
            for (int o = 16; o > 0; o >>= 1)
                found = fmaxf(found, __shfl_xor_sync(0xffffffffu, found, o));
            v11 = found;
        }

        if (lane == 0) {
            const float thres = fmaxf(sigmoidf_(v11), 0.5f);
            const int act = d_actg[b];
            const int an  = d_ang[b];

            float umax = 0.0f, gssel = 0.0f, imax = 0.0f, ineg = 0.0f;
            int g = act ? (__ffs(act) - 1) : -1;
#pragma unroll
            for (int l = 0; l < NL; ++l) {
                float gl = sigmoidf_(fdec(d_gmax[b][l]));
                umax = fmaxf(umax, gl);
                if (l == g) gssel = gl;
                else        imax  = fmaxf(imax, gl);
                if (an & (1 << l)) ineg = fmaxf(ineg, gl);
            }

            float loss;
            if (g < 0) {
                loss = 0.5f * rankl(thres, umax) + 0.5f * rankl(thres, ineg);
            } else {
                loss = rankl(gssel, thres);
                if (imax > 0.0f) loss += 0.5f * rankl(thres, imax);
                loss += 0.5f * ((ineg > 0.0f) ? rankl(thres, ineg)
                                              : rankl(thres, imax));
            }
            d_loss[b] = loss;
        }
    }

    __syncthreads();
    if (tid == 0) {
        __threadfence();
        int done = atomicAdd(&d_done2, 1);
        s_last = (done == NB / 8 - 1);
    }
    __syncthreads();
    if (s_last) {
        __shared__ float sh[BDIM];
        float s = 0.0f;
#pragma unroll
        for (int k = 0; k < NB / BDIM; ++k)
            s += d_loss[tid + k * BDIM];
        sh[tid] = s;
        __syncthreads();
        for (int o = BDIM / 2; o > 0; o >>= 1) {
            if (tid < o) sh[tid] += sh[tid + o];
            __syncthreads();
        }
        if (tid == 0) out[0] = sh[0];
    }
}

extern "C" void kernel_launch(void* const* d_in, const int* in_sizes, int n_in,
                              void* d_out, int out_size) {
    const float* x    = (const float*)d_in[0];
    const int*   y    = (const int*)d_in[1];
    const int*   yn   = (const int*)d_in[2];
    const void*  mask = (const void*)d_in[3];
    float*       out  = (float*)d_out;

    initdetect_kernel<<<256, 256>>>((const unsigned char*)mask);
    build_kernel<<<592, 256>>>(mask);
    scan_kernel<<<GRIDM, BDIM>>>(x, y, yn);
    loss_kernel<<<NB / 8, BDIM>>>(x, out);
}